// round 7
// baseline (speedup 1.0000x reference)
#include <cuda_runtime.h>
#include <cstdint>

// ============================================================================
// Problem constants
// ============================================================================
#define M_DIM 4096
#define K_DIM 4096
#define S_DIM 2048
#define N_DIM 16384            // B*S = 8*2048

#define BM 128
#define BN 256
#define BK 32
#define K_ITERS (K_DIM / BK)   // 128
#define STAGES 4
#define K_OUTER (K_ITERS / STAGES)   // 32

#define THREADS 288            // 8 compute warps (2m x 4n, warp tile 64x64) + 1 producer

// Stage: A 128x32 fp32 (16KB) + B 256x32 fp32 (32KB), packed 32 words/row
#define A_STAGE_BYTES 16384
#define B_STAGE_BYTES 32768
#define STAGE_BYTES   (A_STAGE_BYTES + B_STAGE_BYTES)   // 49152
#define SMEM_STAGE0   1024
#define SMEM_BYTES    (SMEM_STAGE0 + STAGES * STAGE_BYTES)  // 197632

// mbarriers: full[s] at s*16, empty[s] at s*16+8
#define MB_FULL(s)  (s * 16)
#define MB_EMPTY(s) (s * 16 + 8)

// ============================================================================
// Scratch layout (device globals)
//
// Blocked: g_W[kb][m][32], g_X[kb][n][32]  (kb = k/32, chunk = 128B row)
// Within a 32-word chunk, logical k index j (0..31) stored at word c:
//   kk = j>>3 (0..3), kkhi = kk>>1, kklo = kk&1
//   jj = j&7, t = jj&3, half = jj>>2     (half: k=t vs k=t+4 fragment slot)
//   granule = t*2 + ((row&1) ^ kkhi)     (16B granule index, 0..7)
//   c = granule*4 + kklo*2 + half
// => one LDS.128 at granule(t,row,kkhi) yields [kk0_t, kk0_t4, kk1_t, kk1_t4]
//    (fragment pairs for TWO k-steps); 8-lane phases hit 8 distinct granules.
// ============================================================================
__device__ __align__(128) float g_W[(size_t)M_DIM * K_DIM];   // 64 MB
__device__ __align__(128) float g_X[(size_t)N_DIM * K_DIM];   // 256 MB

// ============================================================================
// Helpers
// ============================================================================
__device__ __forceinline__ float tf32_rna(float f) {
    float o;
    asm("cvt.rna.tf32.f32 %0, %1;" : "=f"(o) : "f"(f));
    return o;
}

__device__ __forceinline__ uint32_t smem_u32(const void* p) {
    uint32_t a;
    asm("{ .reg .u64 t; cvta.to.shared.u64 t, %1; cvt.u32.u64 %0, t; }"
        : "=r"(a) : "l"(p));
    return a;
}

__device__ __forceinline__ uint32_t elect_one_pred() {
    uint32_t pred;
    asm volatile(
        "{\n\t.reg .pred p;\n\telect.sync _|p, 0xFFFFFFFF;\n\tselp.b32 %0, 1, 0, p;\n\t}"
        : "=r"(pred));
    return pred;
}

__device__ __forceinline__ uint4 lds128(uint32_t addr) {
    uint4 v;
    asm volatile("ld.shared.v4.u32 {%0,%1,%2,%3}, [%4];"
                 : "=r"(v.x), "=r"(v.y), "=r"(v.z), "=r"(v.w) : "r"(addr));
    return v;
}

__device__ __forceinline__ void mma_tf32(float* c,
                                         uint32_t a0, uint32_t a1,
                                         uint32_t a2, uint32_t a3,
                                         uint32_t b0, uint32_t b1) {
    asm volatile(
        "mma.sync.aligned.m16n8k8.row.col.f32.tf32.tf32.f32 "
        "{%0,%1,%2,%3}, {%4,%5,%6,%7}, {%8,%9}, {%0,%1,%2,%3};"
        : "+f"(c[0]), "+f"(c[1]), "+f"(c[2]), "+f"(c[3])
        : "r"(a0), "r"(a1), "r"(a2), "r"(a3), "r"(b0), "r"(b1));
}

#define MBARRIER_INIT(mbar, count) \
    asm volatile("mbarrier.init.shared.b64 [%0], %1;" \
                 :: "r"((uint32_t)(mbar)), "r"((uint32_t)(count)) : "memory")

#define MBARRIER_ARRIVE(mbar) \
    asm volatile("mbarrier.arrive.shared.b64 _, [%0];" \
                 :: "r"((uint32_t)(mbar)) : "memory")

#define MBARRIER_EXPECT_TX(mbar, tx_bytes) \
    asm volatile("mbarrier.arrive.expect_tx.shared.b64 _, [%0], %1;" \
                 :: "r"((uint32_t)(mbar)), "r"((uint32_t)(tx_bytes)) : "memory")

#define MBARRIER_WAIT_PARITY(mbar, parity) do {                                   \
    uint32_t _mbar = (uint32_t)(mbar);                                            \
    uint32_t _par = (uint32_t)(parity);                                           \
    uint32_t _done;                                                               \
    asm volatile(                                                                 \
        "{\n\t.reg .pred p;\n\t"                                                  \
        "mbarrier.try_wait.parity.acquire.cta.shared::cta.b64 p, [%1], %2;\n\t"   \
        "selp.b32 %0, 1, 0, p;\n\t}"                                              \
        : "=r"(_done) : "r"(_mbar), "r"(_par) : "memory");                        \
    if (!_done) {                                                                 \
        asm volatile(                                                             \
            "{\n\t.reg .pred P1;\n\t"                                             \
            "WAIT_LOOP_%=:\n\t"                                                   \
            "mbarrier.try_wait.parity.acquire.cta.shared::cta.b64 P1, [%0], %1, 0x989680;\n\t" \
            "@P1 bra.uni WAIT_DONE_%=;\n\t"                                       \
            "bra.uni WAIT_LOOP_%=;\n\t"                                           \
            "WAIT_DONE_%=:\n\t}"                                                  \
            :: "r"(_mbar), "r"(_par) : "memory");                                 \
    }                                                                             \
} while (0)

#define MBARRIER_WAIT_PARITY_RELAXED(mbar, parity) do {                           \
    uint32_t _mbar = (uint32_t)(mbar);                                            \
    uint32_t _par = (uint32_t)(parity);                                           \
    uint32_t _done;                                                               \
    asm volatile(                                                                 \
        "{\n\t.reg .pred p;\n\t"                                                  \
        "mbarrier.try_wait.parity.relaxed.cta.shared::cta.b64 p, [%1], %2, 0x989680;\n\t" \
        "selp.b32 %0, 1, 0, p;\n\t}"                                              \
        : "=r"(_done) : "r"(_mbar), "r"(_par) : "memory");                        \
    if (!_done) {                                                                 \
        asm volatile(                                                             \
            "{\n\t.reg .pred P1;\n\t"                                             \
            "WAIT_LOOP_%=:\n\t"                                                   \
            "mbarrier.try_wait.parity.relaxed.cta.shared::cta.b64 P1, [%0], %1, 0x989680;\n\t" \
            "@P1 bra.uni WAIT_DONE_%=;\n\t"                                       \
            "bra.uni WAIT_LOOP_%=;\n\t"                                           \
            "WAIT_DONE_%=:\n\t}"                                                  \
            :: "r"(_mbar), "r"(_par) : "memory");                                 \
    }                                                                             \
} while (0)

#define BULK_G2S(dst_smem, src_gmem, nbytes, mbar)                                \
    asm volatile(                                                                 \
        "cp.async.bulk.shared::cta.global.mbarrier::complete_tx::bytes "          \
        "[%0], [%1], %2, [%3];"                                                   \
        :: "r"((uint32_t)(dst_smem)), "l"(src_gmem),                              \
           "r"((uint32_t)(nbytes)), "r"((uint32_t)(mbar)) : "memory")

// Word index inside a 32-word chunk for logical k-offset j in row `row`.
__host__ __device__ __forceinline__ int chunk_word(int row, int j) {
    int kk = j >> 3, kkhi = kk >> 1, kklo = kk & 1;
    int jj = j & 7, t = jj & 3, half = jj >> 2;
    int granule = t * 2 + ((row & 1) ^ kkhi);
    return granule * 4 + kklo * 2 + half;
}

// ============================================================================
// Pre-pass kernels
// ============================================================================
__global__ void scatter_kernel(const float* __restrict__ vals,
                               const int* __restrict__ rows,
                               const int* __restrict__ cols, int nnz) {
    int i = blockIdx.x * blockDim.x + threadIdx.x;
    if (i < nnz) {
        int r = rows[i], c = cols[i];
        int kb = c >> 5;
        int cc = chunk_word(r, c & 31);
        atomicAdd(&g_W[(size_t)kb * (M_DIM * 32) + (size_t)r * 32 + cc], vals[i]);
    }
}

// Elementwise tf32-round of W (layout-independent, in place).
__global__ void round_w_kernel() {
    size_t n4 = (size_t)M_DIM * K_DIM / 4;
    float4* p = reinterpret_cast<float4*>(g_W);
    for (size_t i = blockIdx.x * blockDim.x + threadIdx.x; i < n4;
         i += (size_t)gridDim.x * blockDim.x) {
        float4 v = p[i];
        v.x = tf32_rna(v.x); v.y = tf32_rna(v.y);
        v.z = tf32_rna(v.z); v.w = tf32_rna(v.w);
        p[i] = v;
    }
}

// x -> g_X: tf32 round + k-blocked + chunk permutation. One thread per 32-word
// chunk: reads 128B contiguous, writes 128B contiguous (permuted inside).
__global__ void conv_x_kernel(const float* __restrict__ x) {
    size_t nchunks = (size_t)N_DIM * (K_DIM / 32);    // 2M
    for (size_t i = blockIdx.x * blockDim.x + threadIdx.x; i < nchunks;
         i += (size_t)gridDim.x * blockDim.x) {
        int n  = (int)(i >> 7);            // K/32 = 128 chunks per row
        int kb = (int)(i & 127);
        const float* src = x + (size_t)n * K_DIM + kb * 32;
        float o[32];
        #pragma unroll
        for (int j = 0; j < 32; j++) {
            o[chunk_word(n, j)] = tf32_rna(src[j]);
        }
        float4* dst = reinterpret_cast<float4*>(
            g_X + (size_t)kb * (N_DIM * 32) + (size_t)n * 32);
        #pragma unroll
        for (int q = 0; q < 8; q++) {
            dst[q] = make_float4(o[4*q], o[4*q+1], o[4*q+2], o[4*q+3]);
        }
    }
}

// ============================================================================
// Warp-specialized tf32 GEMM with cp.async.bulk producer.
// out[b,m,s] = sum_k W[m,k] * X[n,k] + bias[s],  n = b*2048 + s
// ============================================================================
__global__ void __launch_bounds__(THREADS, 1) gemm_kernel(
    const float* __restrict__ bias, float* __restrict__ out)
{
    extern __shared__ uint32_t smem[];
    const uint32_t sbase = smem_u32(smem);

    const int tid  = threadIdx.x;
    const int wid  = tid >> 5;
    const int lane = tid & 31;

    // CTA tile mapping: bid = mt + 32*nt (wave covers all m-tiles -> A reuse)
    const int mt = blockIdx.x & 31;
    const int nt = blockIdx.x >> 5;
    const int m0 = mt * BM;
    const int n0 = nt * BN;

    if (tid == 0) {
        #pragma unroll
        for (int s = 0; s < STAGES; s++) {
            MBARRIER_INIT(sbase + MB_FULL(s), 1);
            MBARRIER_INIT(sbase + MB_EMPTY(s), 8);
        }
    }
    __syncthreads();

    if (wid == 8) {
        // ------------------------- Producer warp -------------------------
        if (elect_one_pred()) {
            const float* Asrc0 = g_W + (size_t)m0 * 32;
            const float* Bsrc0 = g_X + (size_t)n0 * 32;
            int ph = 1;   // fresh barriers: parity-1 waits pass
            for (int ko = 0; ko < K_OUTER; ko++) {
                #pragma unroll
                for (int s = 0; s < STAGES; s++) {
                    const int k = ko * STAGES + s;
                    MBARRIER_WAIT_PARITY_RELAXED(sbase + MB_EMPTY(s), ph);
                    uint32_t full = sbase + MB_FULL(s);
                    uint32_t dst  = sbase + SMEM_STAGE0 + s * STAGE_BYTES;
                    MBARRIER_EXPECT_TX(full, STAGE_BYTES);
                    BULK_G2S(dst, Asrc0 + (size_t)k * (M_DIM * 32),
                             A_STAGE_BYTES, full);
                    BULK_G2S(dst + A_STAGE_BYTES, Bsrc0 + (size_t)k * (N_DIM * 32),
                             B_STAGE_BYTES, full);
                }
                ph ^= 1;
            }
        }
        return;
    }

    // --------------------------- Consumer warps ---------------------------
    const int g  = lane >> 2;       // fragment row group 0..7
    const int t  = lane & 3;        // fragment col group 0..3
    const int wm = wid & 1;         // warp m index 0..1
    const int wn = wid >> 1;        // warp n index 0..3

    // kkhi=0 fragment base addresses (granule = t*2 + (g&1)); kkhi=1 = base^16.
    uint32_t aAddr[2], bAddr[2];
    {
        const uint32_t gb = (uint32_t)((t * 2 + (g & 1)) * 16);
        aAddr[0] = sbase + SMEM_STAGE0
                 + (uint32_t)((wm * 64 + g) * 128) + gb;
        aAddr[1] = aAddr[0] ^ 16u;
        bAddr[0] = sbase + SMEM_STAGE0 + A_STAGE_BYTES
                 + (uint32_t)((wn * 64 + g) * 128) + gb;
        bAddr[1] = bAddr[0] ^ 16u;
    }

    float acc[4][8][4];
#pragma unroll
    for (int i = 0; i < 4; i++)
#pragma unroll
        for (int j = 0; j < 8; j++)
#pragma unroll
            for (int r = 0; r < 4; r++) acc[i][j][r] = 0.0f;

    int ph = 0;
    for (int ko = 0; ko < K_OUTER; ko++) {
        #pragma unroll
        for (int s = 0; s < STAGES; s++) {
            MBARRIER_WAIT_PARITY(sbase + MB_FULL(s), ph);
            const uint32_t soff = (uint32_t)(s * STAGE_BYTES);

            #pragma unroll
            for (int kh = 0; kh < 2; kh++) {
                // A fragments for 2 k-steps: rows g (aF0) and g+8 (aF1)
                uint4 aF0[4], aF1[4];
                #pragma unroll
                for (int mi = 0; mi < 4; mi++) {
                    const uint32_t ab = aAddr[kh] + soff + (uint32_t)(mi * 2048);
                    aF0[mi] = lds128(ab);
                    aF1[mi] = lds128(ab + 1024);
                }
                #pragma unroll
                for (int nh = 0; nh < 2; nh++) {
                    uint4 bF[4];
                    #pragma unroll
                    for (int nj = 0; nj < 4; nj++) {
                        bF[nj] = lds128(bAddr[kh] + soff
                                        + (uint32_t)((nh * 4 + nj) * 1024));
                    }
                    // k-step kklo=0 (.x/.y), then kklo=1 (.z/.w)
                    #pragma unroll
                    for (int nj = 0; nj < 4; nj++) {
                        #pragma unroll
                        for (int mi = 0; mi < 4; mi++) {
                            mma_tf32(acc[mi][nh * 4 + nj],
                                     aF0[mi].x, aF1[mi].x, aF0[mi].y, aF1[mi].y,
                                     bF[nj].x, bF[nj].y);
                        }
                    }
                    #pragma unroll
                    for (int nj = 0; nj < 4; nj++) {
                        #pragma unroll
                        for (int mi = 0; mi < 4; mi++) {
                            mma_tf32(acc[mi][nh * 4 + nj],
                                     aF0[mi].z, aF1[mi].z, aF0[mi].w, aF1[mi].w,
                                     bF[nj].z, bF[nj].w);
                        }
                    }
                }
            }

            __syncwarp();
            if (lane == 0) MBARRIER_ARRIVE(sbase + MB_EMPTY(s));
        }
        ph ^= 1;
    }

    // ------------------------------------------------------------------------
    // Epilogue: out[b, m, s] = acc + bias[s]; CTA tile lies in one batch
    // ------------------------------------------------------------------------
    const int b   = n0 >> 11;        // n0 / 2048
    const int s0c = n0 & 2047;
    float* obase = out + (size_t)b * M_DIM * S_DIM;

#pragma unroll
    for (int mi = 0; mi < 4; mi++) {
#pragma unroll
        for (int ni = 0; ni < 8; ni++) {
            int sl = s0c + wn * 64 + ni * 8 + 2 * t;
            float2 bv = *reinterpret_cast<const float2*>(bias + sl);
            int m = m0 + wm * 64 + mi * 16 + g;

            float2 v0;
            v0.x = acc[mi][ni][0] + bv.x;
            v0.y = acc[mi][ni][1] + bv.y;
            *reinterpret_cast<float2*>(obase + (size_t)m * S_DIM + sl) = v0;

            float2 v1;
            v1.x = acc[mi][ni][2] + bv.x;
            v1.y = acc[mi][ni][3] + bv.y;
            *reinterpret_cast<float2*>(obase + (size_t)(m + 8) * S_DIM + sl) = v1;
        }
    }
}

// ============================================================================
// Host launch
// ============================================================================
extern "C" void kernel_launch(void* const* d_in, const int* in_sizes, int n_in,
                              void* d_out, int out_size) {
    const float* x      = (const float*)d_in[0];
    const float* values = (const float*)d_in[1];
    const float* bias   = (const float*)d_in[2];
    const int* row_ids  = (const int*)d_in[3];
    const int* col_idx  = (const int*)d_in[4];
    int nnz = in_sizes[1];
    float* out = (float*)d_out;

    void* wptr = nullptr;
    cudaGetSymbolAddress(&wptr, g_W);

    // 1) zero W (each replay re-accumulates from zero)
    cudaMemsetAsync(wptr, 0, (size_t)M_DIM * K_DIM * sizeof(float));

    // 2) scatter-add COO values directly into blocked+permuted W
    scatter_kernel<<<(nnz + 255) / 256, 256>>>(values, row_ids, col_idx, nnz);

    // 3) tf32-round W in place; build blocked+permuted tf32 X
    round_w_kernel<<<2048, 256>>>();
    conv_x_kernel<<<4096, 256>>>(x);

    // 4) GEMM
    cudaFuncSetAttribute(gemm_kernel,
                         cudaFuncAttributeMaxDynamicSharedMemorySize,
                         SMEM_BYTES);
    gemm_kernel<<<(M_DIM / BM) * (N_DIM / BN), THREADS, SMEM_BYTES>>>(bias, out);
}

// round 8
// speedup vs baseline: 1.2910x; 1.2910x over previous
#include <cuda_runtime.h>
#include <cstdint>

// ============================================================================
// Problem constants
// ============================================================================
#define M_DIM 4096
#define K_DIM 4096
#define S_DIM 2048
#define N_DIM 16384            // B*S = 8*2048

#define BM 128
#define BN 256
#define BK 32
#define K_ITERS (K_DIM / BK)   // 128
#define STAGES 4
#define K_OUTER (K_ITERS / STAGES)   // 32

#define THREADS 288            // 8 compute warps (2m x 4n, warp tile 64x64) + 1 producer

// Stage: A 128x32 fp32 (16KB) + B 256x32 fp32 (32KB), packed 32 words/row
#define A_STAGE_BYTES 16384
#define B_STAGE_BYTES 32768
#define STAGE_BYTES   (A_STAGE_BYTES + B_STAGE_BYTES)   // 49152
#define SMEM_STAGE0   1024
#define SMEM_BYTES    (SMEM_STAGE0 + STAGES * STAGE_BYTES)  // 197632

// mbarriers: full[s] at s*16, empty[s] at s*16+8
#define MB_FULL(s)  ((s) * 16)
#define MB_EMPTY(s) ((s) * 16 + 8)

// ============================================================================
// Scratch layout (device globals) — identical to the validated R5 layout.
//
// Blocked: g_W[kb][m][32], g_X[kb][n][32]  (kb = k/32, chunk = 128B row)
// Within a 32-word chunk, logical k index j (0..31) stored at word c:
//   kk = j>>3, jj = j&7
//   p  = jj<4 ? 2*jj : 2*(jj-4)+1          (pair perm: [k0,k4,k1,k5,...])
//   c  = ((kk ^ (row & 3)) << 3) | p       (XOR swizzle -> conflict-free LDS.64)
// ============================================================================
__device__ __align__(128) float g_W[(size_t)M_DIM * K_DIM];   // 64 MB
__device__ __align__(128) float g_X[(size_t)N_DIM * K_DIM];   // 256 MB

// ============================================================================
// Helpers
// ============================================================================
__device__ __forceinline__ float tf32_rna(float f) {
    float o;
    asm("cvt.rna.tf32.f32 %0, %1;" : "=f"(o) : "f"(f));
    return o;
}

__device__ __forceinline__ uint32_t smem_u32(const void* p) {
    uint32_t a;
    asm("{ .reg .u64 t; cvta.to.shared.u64 t, %1; cvt.u32.u64 %0, t; }"
        : "=r"(a) : "l"(p));
    return a;
}

__device__ __forceinline__ uint32_t elect_one_pred() {
    uint32_t pred;
    asm volatile(
        "{\n\t.reg .pred p;\n\telect.sync _|p, 0xFFFFFFFF;\n\tselp.b32 %0, 1, 0, p;\n\t}"
        : "=r"(pred));
    return pred;
}

// LDS.64 with compile-time immediate offset baked into the addressing mode:
// SASS = LDS.64 Rd, [Ra+IMM]; no companion IADD.
template <int IMM>
__device__ __forceinline__ uint2 lds64i(uint32_t addr) {
    uint2 v;
    asm volatile("ld.shared.v2.u32 {%0,%1}, [%2+%3];"
                 : "=r"(v.x), "=r"(v.y) : "r"(addr), "n"(IMM));
    return v;
}

__device__ __forceinline__ void mma_tf32(float* c,
                                         uint32_t a0, uint32_t a1,
                                         uint32_t a2, uint32_t a3,
                                         uint32_t b0, uint32_t b1) {
    asm volatile(
        "mma.sync.aligned.m16n8k8.row.col.f32.tf32.tf32.f32 "
        "{%0,%1,%2,%3}, {%4,%5,%6,%7}, {%8,%9}, {%0,%1,%2,%3};"
        : "+f"(c[0]), "+f"(c[1]), "+f"(c[2]), "+f"(c[3])
        : "r"(a0), "r"(a1), "r"(a2), "r"(a3), "r"(b0), "r"(b1));
}

#define MBARRIER_INIT(mbar, count) \
    asm volatile("mbarrier.init.shared.b64 [%0], %1;" \
                 :: "r"((uint32_t)(mbar)), "r"((uint32_t)(count)) : "memory")

#define MBARRIER_ARRIVE(mbar) \
    asm volatile("mbarrier.arrive.shared.b64 _, [%0];" \
                 :: "r"((uint32_t)(mbar)) : "memory")

#define MBARRIER_EXPECT_TX(mbar, tx_bytes) \
    asm volatile("mbarrier.arrive.expect_tx.shared.b64 _, [%0], %1;" \
                 :: "r"((uint32_t)(mbar)), "r"((uint32_t)(tx_bytes)) : "memory")

#define MBARRIER_WAIT_PARITY(mbar, parity) do {                                   \
    uint32_t _mbar = (uint32_t)(mbar);                                            \
    uint32_t _par = (uint32_t)(parity);                                           \
    uint32_t _done;                                                               \
    asm volatile(                                                                 \
        "{\n\t.reg .pred p;\n\t"                                                  \
        "mbarrier.try_wait.parity.acquire.cta.shared::cta.b64 p, [%1], %2;\n\t"   \
        "selp.b32 %0, 1, 0, p;\n\t}"                                              \
        : "=r"(_done) : "r"(_mbar), "r"(_par) : "memory");                        \
    if (!_done) {                                                                 \
        asm volatile(                                                             \
            "{\n\t.reg .pred P1;\n\t"                                             \
            "WAIT_LOOP_%=:\n\t"                                                   \
            "mbarrier.try_wait.parity.acquire.cta.shared::cta.b64 P1, [%0], %1, 0x989680;\n\t" \
            "@P1 bra.uni WAIT_DONE_%=;\n\t"                                       \
            "bra.uni WAIT_LOOP_%=;\n\t"                                           \
            "WAIT_DONE_%=:\n\t}"                                                  \
            :: "r"(_mbar), "r"(_par) : "memory");                                 \
    }                                                                             \
} while (0)

#define MBARRIER_WAIT_PARITY_RELAXED(mbar, parity) do {                           \
    uint32_t _mbar = (uint32_t)(mbar);                                            \
    uint32_t _par = (uint32_t)(parity);                                           \
    uint32_t _done;                                                               \
    asm volatile(                                                                 \
        "{\n\t.reg .pred p;\n\t"                                                  \
        "mbarrier.try_wait.parity.relaxed.cta.shared::cta.b64 p, [%1], %2, 0x989680;\n\t" \
        "selp.b32 %0, 1, 0, p;\n\t}"                                              \
        : "=r"(_done) : "r"(_mbar), "r"(_par) : "memory");                        \
    if (!_done) {                                                                 \
        asm volatile(                                                             \
            "{\n\t.reg .pred P1;\n\t"                                             \
            "WAIT_LOOP_%=:\n\t"                                                   \
            "mbarrier.try_wait.parity.relaxed.cta.shared::cta.b64 P1, [%0], %1, 0x989680;\n\t" \
            "@P1 bra.uni WAIT_DONE_%=;\n\t"                                       \
            "bra.uni WAIT_LOOP_%=;\n\t"                                           \
            "WAIT_DONE_%=:\n\t}"                                                  \
            :: "r"(_mbar), "r"(_par) : "memory");                                 \
    }                                                                             \
} while (0)

#define BULK_G2S(dst_smem, src_gmem, nbytes, mbar)                                \
    asm volatile(                                                                 \
        "cp.async.bulk.shared::cta.global.mbarrier::complete_tx::bytes "          \
        "[%0], [%1], %2, [%3];"                                                   \
        :: "r"((uint32_t)(dst_smem)), "l"(src_gmem),                              \
           "r"((uint32_t)(nbytes)), "r"((uint32_t)(mbar)) : "memory")

// ============================================================================
// Pre-pass kernels (identical to validated R5)
// ============================================================================
__global__ void scatter_kernel(const float* __restrict__ vals,
                               const int* __restrict__ rows,
                               const int* __restrict__ cols, int nnz) {
    int i = blockIdx.x * blockDim.x + threadIdx.x;
    if (i < nnz) {
        int r = rows[i], c = cols[i];
        int kb = c >> 5, j = c & 31, kk = j >> 3, jj = j & 7;
        int p = (jj < 4) ? (jj << 1) : (((jj - 4) << 1) | 1);
        int cc = ((kk ^ (r & 3)) << 3) | p;
        atomicAdd(&g_W[(size_t)kb * (M_DIM * 32) + (size_t)r * 32 + cc], vals[i]);
    }
}

__global__ void round_w_kernel() {
    size_t n4 = (size_t)M_DIM * K_DIM / 4;
    float4* p = reinterpret_cast<float4*>(g_W);
    for (size_t i = blockIdx.x * blockDim.x + threadIdx.x; i < n4;
         i += (size_t)gridDim.x * blockDim.x) {
        float4 v = p[i];
        v.x = tf32_rna(v.x); v.y = tf32_rna(v.y);
        v.z = tf32_rna(v.z); v.w = tf32_rna(v.w);
        p[i] = v;
    }
}

__global__ void conv_x_kernel(const float* __restrict__ x) {
    size_t ngroups = (size_t)N_DIM * (K_DIM / 8);
    for (size_t i = blockIdx.x * blockDim.x + threadIdx.x; i < ngroups;
         i += (size_t)gridDim.x * blockDim.x) {
        int n  = (int)(i >> 9);            // K/8 = 512 groups per row
        int k8 = (int)(i & 511);
        int kb = k8 >> 2, kk = k8 & 3;
        const float4* src = reinterpret_cast<const float4*>(x + (size_t)n * K_DIM + k8 * 8);
        float4 v0 = src[0];                // k0..k3
        float4 v1 = src[1];                // k4..k7
        float4 o0, o1;
        o0.x = tf32_rna(v0.x); o0.y = tf32_rna(v1.x);   // k0,k4
        o0.z = tf32_rna(v0.y); o0.w = tf32_rna(v1.y);   // k1,k5
        o1.x = tf32_rna(v0.z); o1.y = tf32_rna(v1.z);   // k2,k6
        o1.z = tf32_rna(v0.w); o1.w = tf32_rna(v1.w);   // k3,k7
        float* dst = g_X + (size_t)kb * (N_DIM * 32) + (size_t)n * 32
                         + ((kk ^ (n & 3)) << 3);
        reinterpret_cast<float4*>(dst)[0] = o0;
        reinterpret_cast<float4*>(dst)[1] = o1;
    }
}

// ============================================================================
// Mainloop body macros: all SMEM offsets are literal immediates.
// ============================================================================
#define MMA_ROWS(ni, bf)                                                        \
    mma_tf32(acc[0][ni], alo0.x, ahi0.x, alo0.y, ahi0.y, (bf).x, (bf).y);       \
    mma_tf32(acc[1][ni], alo1.x, ahi1.x, alo1.y, ahi1.y, (bf).x, (bf).y);       \
    mma_tf32(acc[2][ni], alo2.x, ahi2.x, alo2.y, ahi2.y, (bf).x, (bf).y);       \
    mma_tf32(acc[3][ni], alo3.x, ahi3.x, alo3.y, ahi3.y, (bf).x, (bf).y);

#define KK_BLOCK(S, KKI) do {                                                   \
    uint2 alo0 = lds64i<(S)*STAGE_BYTES +    0>(aAddr[KKI]);                    \
    uint2 ahi0 = lds64i<(S)*STAGE_BYTES + 1024>(aAddr[KKI]);                    \
    uint2 alo1 = lds64i<(S)*STAGE_BYTES + 2048>(aAddr[KKI]);                    \
    uint2 ahi1 = lds64i<(S)*STAGE_BYTES + 3072>(aAddr[KKI]);                    \
    uint2 alo2 = lds64i<(S)*STAGE_BYTES + 4096>(aAddr[KKI]);                    \
    uint2 ahi2 = lds64i<(S)*STAGE_BYTES + 5120>(aAddr[KKI]);                    \
    uint2 alo3 = lds64i<(S)*STAGE_BYTES + 6144>(aAddr[KKI]);                    \
    uint2 ahi3 = lds64i<(S)*STAGE_BYTES + 7168>(aAddr[KKI]);                    \
    uint2 b0 = lds64i<(S)*STAGE_BYTES +    0>(bAddr[KKI]);                      \
    uint2 b1 = lds64i<(S)*STAGE_BYTES + 1024>(bAddr[KKI]);                      \
    uint2 b2 = lds64i<(S)*STAGE_BYTES + 2048>(bAddr[KKI]);                      \
    uint2 b3 = lds64i<(S)*STAGE_BYTES + 3072>(bAddr[KKI]);                      \
    uint2 b4 = lds64i<(S)*STAGE_BYTES + 4096>(bAddr[KKI]);                      \
    uint2 b5 = lds64i<(S)*STAGE_BYTES + 5120>(bAddr[KKI]);                      \
    uint2 b6 = lds64i<(S)*STAGE_BYTES + 6144>(bAddr[KKI]);                      \
    uint2 b7 = lds64i<(S)*STAGE_BYTES + 7168>(bAddr[KKI]);                      \
    MMA_ROWS(0, b0); MMA_ROWS(1, b1); MMA_ROWS(2, b2); MMA_ROWS(3, b3);         \
    MMA_ROWS(4, b4); MMA_ROWS(5, b5); MMA_ROWS(6, b6); MMA_ROWS(7, b7);         \
} while (0)

#define CONSUME_STAGE(S) do {                                                   \
    MBARRIER_WAIT_PARITY(sbase + MB_FULL(S), ph);                               \
    KK_BLOCK(S, 0); KK_BLOCK(S, 1); KK_BLOCK(S, 2); KK_BLOCK(S, 3);             \
    __syncwarp();                                                               \
    if (lane == 0) MBARRIER_ARRIVE(sbase + MB_EMPTY(S));                        \
} while (0)

// ============================================================================
// Warp-specialized tf32 GEMM with cp.async.bulk producer.
// out[b,m,s] = sum_k W[m,k] * X[n,k] + bias[s],  n = b*2048 + s
// ============================================================================
__global__ void __launch_bounds__(THREADS, 1) gemm_kernel(
    const float* __restrict__ bias, float* __restrict__ out)
{
    extern __shared__ uint32_t smem[];
    const uint32_t sbase = smem_u32(smem);

    const int tid  = threadIdx.x;
    const int wid  = tid >> 5;
    const int lane = tid & 31;

    // CTA tile mapping: bid = mt + 32*nt (wave covers all m-tiles -> A reuse)
    const int mt = blockIdx.x & 31;
    const int nt = blockIdx.x >> 5;
    const int m0 = mt * BM;
    const int n0 = nt * BN;

    if (tid == 0) {
        #pragma unroll
        for (int s = 0; s < STAGES; s++) {
            MBARRIER_INIT(sbase + MB_FULL(s), 1);
            MBARRIER_INIT(sbase + MB_EMPTY(s), 8);
        }
    }
    __syncthreads();

    if (wid == 8) {
        // ------------------------- Producer warp -------------------------
        if (elect_one_pred()) {
            const float* Asrc0 = g_W + (size_t)m0 * 32;
            const float* Bsrc0 = g_X + (size_t)n0 * 32;
            int ph = 1;   // fresh barriers: parity-1 waits pass
            for (int ko = 0; ko < K_OUTER; ko++) {
                #pragma unroll
                for (int s = 0; s < STAGES; s++) {
                    const int k = ko * STAGES + s;
                    MBARRIER_WAIT_PARITY_RELAXED(sbase + MB_EMPTY(s), ph);
                    uint32_t full = sbase + MB_FULL(s);
                    uint32_t dst  = sbase + SMEM_STAGE0 + s * STAGE_BYTES;
                    MBARRIER_EXPECT_TX(full, STAGE_BYTES);
                    BULK_G2S(dst, Asrc0 + (size_t)k * (M_DIM * 32),
                             A_STAGE_BYTES, full);
                    BULK_G2S(dst + A_STAGE_BYTES, Bsrc0 + (size_t)k * (N_DIM * 32),
                             B_STAGE_BYTES, full);
                }
                ph ^= 1;
            }
        }
        return;
    }

    // --------------------------- Consumer warps ---------------------------
    const int g  = lane >> 2;       // fragment row group 0..7
    const int t  = lane & 3;        // fragment col group 0..3
    const int gx = g & 3;           // XOR swizzle key
    const int wm = wid & 1;         // warp m index 0..1
    const int wn = wid >> 1;        // warp n index 0..3

    // Per-kk stage-0 base addresses; stage & mi/ni offsets are LDS immediates.
    uint32_t aAddr[4], bAddr[4];
    {
        const uint32_t aBase = sbase + SMEM_STAGE0
                             + (uint32_t)((wm * 64 + g) * 128 + t * 8);
        const uint32_t bBase = sbase + SMEM_STAGE0 + A_STAGE_BYTES
                             + (uint32_t)((wn * 64 + g) * 128 + t * 8);
        #pragma unroll
        for (int kk = 0; kk < 4; kk++) {
            const uint32_t kx = (uint32_t)(((kk ^ gx) & 3) << 5);
            aAddr[kk] = aBase + kx;
            bAddr[kk] = bBase + kx;
        }
    }

    float acc[4][8][4];
#pragma unroll
    for (int i = 0; i < 4; i++)
#pragma unroll
        for (int j = 0; j < 8; j++)
#pragma unroll
            for (int r = 0; r < 4; r++) acc[i][j][r] = 0.0f;

    int ph = 0;
    for (int ko = 0; ko < K_OUTER; ko++) {
        CONSUME_STAGE(0);
        CONSUME_STAGE(1);
        CONSUME_STAGE(2);
        CONSUME_STAGE(3);
        ph ^= 1;
    }

    // ------------------------------------------------------------------------
    // Epilogue: out[b, m, s] = acc + bias[s]; CTA tile lies in one batch
    // ------------------------------------------------------------------------
    const int b   = n0 >> 11;        // n0 / 2048
    const int s0c = n0 & 2047;
    float* obase = out + (size_t)b * M_DIM * S_DIM;

#pragma unroll
    for (int mi = 0; mi < 4; mi++) {
#pragma unroll
        for (int ni = 0; ni < 8; ni++) {
            int sl = s0c + wn * 64 + ni * 8 + 2 * t;
            float2 bv = *reinterpret_cast<const float2*>(bias + sl);
            int m = m0 + wm * 64 + mi * 16 + g;

            float2 v0;
            v0.x = acc[mi][ni][0] + bv.x;
            v0.y = acc[mi][ni][1] + bv.y;
            *reinterpret_cast<float2*>(obase + (size_t)m * S_DIM + sl) = v0;

            float2 v1;
            v1.x = acc[mi][ni][2] + bv.x;
            v1.y = acc[mi][ni][3] + bv.y;
            *reinterpret_cast<float2*>(obase + (size_t)(m + 8) * S_DIM + sl) = v1;
        }
    }
}

// ============================================================================
// Host launch
// ============================================================================
extern "C" void kernel_launch(void* const* d_in, const int* in_sizes, int n_in,
                              void* d_out, int out_size) {
    const float* x      = (const float*)d_in[0];
    const float* values = (const float*)d_in[1];
    const float* bias   = (const float*)d_in[2];
    const int* row_ids  = (const int*)d_in[3];
    const int* col_idx  = (const int*)d_in[4];
    int nnz = in_sizes[1];
    float* out = (float*)d_out;

    void* wptr = nullptr;
    cudaGetSymbolAddress(&wptr, g_W);

    // 1) zero W (each replay re-accumulates from zero)
    cudaMemsetAsync(wptr, 0, (size_t)M_DIM * K_DIM * sizeof(float));

    // 2) scatter-add COO values directly into blocked+swizzled W
    scatter_kernel<<<(nnz + 255) / 256, 256>>>(values, row_ids, col_idx, nnz);

    // 3) tf32-round W in place; build blocked+swizzled tf32 X
    round_w_kernel<<<2048, 256>>>();
    conv_x_kernel<<<4096, 256>>>(x);

    // 4) GEMM
    cudaFuncSetAttribute(gemm_kernel,
                         cudaFuncAttributeMaxDynamicSharedMemorySize,
                         SMEM_BYTES);
    gemm_kernel<<<(M_DIM / BM) * (N_DIM / BN), THREADS, SMEM_BYTES>>>(bias, out);
}

// round 9
// speedup vs baseline: 1.9676x; 1.5242x over previous
#include <cuda_runtime.h>
#include <cstdint>

// ============================================================================
// Problem constants
// ============================================================================
#define M_DIM 4096
#define K_DIM 4096
#define S_DIM 2048
#define N_DIM 16384            // B*S = 8*2048

#define BM 256
#define BN 128
#define BK 32
#define K_ITERS (K_DIM / BK)   // 128
#define STAGES 4
#define K_OUTER (K_ITERS / STAGES)   // 32

#define THREADS 544            // 16 compute warps (4m x 4n, warp tile 64x32) + 1 producer

// Stage: A 256x32 fp32 (32KB) + B 128x32 fp32 (16KB), packed 32 words/row
#define A_STAGE_BYTES 32768
#define B_STAGE_BYTES 16384
#define STAGE_BYTES   (A_STAGE_BYTES + B_STAGE_BYTES)   // 49152
#define SMEM_STAGE0   1024
#define SMEM_BYTES    (SMEM_STAGE0 + STAGES * STAGE_BYTES)  // 197632

// mbarriers: full[s] at s*16, empty[s] at s*16+8
#define MB_FULL(s)  ((s) * 16)
#define MB_EMPTY(s) ((s) * 16 + 8)

// ============================================================================
// Scratch layout (device globals) — validated R5 chunk layout.
//
// Blocked: g_W[kb][m][32], g_X[kb][n][32]  (kb = k/32, chunk = 128B row)
// Within a 32-word chunk, logical k index j (0..31) stored at word c:
//   kk = j>>3, jj = j&7
//   p  = jj<4 ? 2*jj : 2*(jj-4)+1          (pair perm: [k0,k4,k1,k5,...])
//   c  = ((kk ^ (row & 3)) << 3) | p       (XOR swizzle -> conflict-free LDS.64)
// ============================================================================
__device__ __align__(128) float g_W[(size_t)M_DIM * K_DIM];   // 64 MB
__device__ __align__(128) float g_X[(size_t)N_DIM * K_DIM];   // 256 MB

// ============================================================================
// Helpers
// ============================================================================
__device__ __forceinline__ float tf32_rna(float f) {
    float o;
    asm("cvt.rna.tf32.f32 %0, %1;" : "=f"(o) : "f"(f));
    return o;
}

__device__ __forceinline__ uint32_t smem_u32(const void* p) {
    uint32_t a;
    asm("{ .reg .u64 t; cvta.to.shared.u64 t, %1; cvt.u32.u64 %0, t; }"
        : "=r"(a) : "l"(p));
    return a;
}

__device__ __forceinline__ uint32_t elect_one_pred() {
    uint32_t pred;
    asm volatile(
        "{\n\t.reg .pred p;\n\telect.sync _|p, 0xFFFFFFFF;\n\tselp.b32 %0, 1, 0, p;\n\t}"
        : "=r"(pred));
    return pred;
}

// LDS.64 with compile-time immediate offset in the addressing mode.
template <int IMM>
__device__ __forceinline__ uint2 lds64i(uint32_t addr) {
    uint2 v;
    asm volatile("ld.shared.v2.u32 {%0,%1}, [%2+%3];"
                 : "=r"(v.x), "=r"(v.y) : "r"(addr), "n"(IMM));
    return v;
}

__device__ __forceinline__ void mma_tf32(float* c,
                                         uint32_t a0, uint32_t a1,
                                         uint32_t a2, uint32_t a3,
                                         uint32_t b0, uint32_t b1) {
    asm volatile(
        "mma.sync.aligned.m16n8k8.row.col.f32.tf32.tf32.f32 "
        "{%0,%1,%2,%3}, {%4,%5,%6,%7}, {%8,%9}, {%0,%1,%2,%3};"
        : "+f"(c[0]), "+f"(c[1]), "+f"(c[2]), "+f"(c[3])
        : "r"(a0), "r"(a1), "r"(a2), "r"(a3), "r"(b0), "r"(b1));
}

#define MBARRIER_INIT(mbar, count) \
    asm volatile("mbarrier.init.shared.b64 [%0], %1;" \
                 :: "r"((uint32_t)(mbar)), "r"((uint32_t)(count)) : "memory")

#define MBARRIER_ARRIVE(mbar) \
    asm volatile("mbarrier.arrive.shared.b64 _, [%0];" \
                 :: "r"((uint32_t)(mbar)) : "memory")

#define MBARRIER_EXPECT_TX(mbar, tx_bytes) \
    asm volatile("mbarrier.arrive.expect_tx.shared.b64 _, [%0], %1;" \
                 :: "r"((uint32_t)(mbar)), "r"((uint32_t)(tx_bytes)) : "memory")

#define MBARRIER_WAIT_PARITY(mbar, parity) do {                                   \
    uint32_t _mbar = (uint32_t)(mbar);                                            \
    uint32_t _par = (uint32_t)(parity);                                           \
    uint32_t _done;                                                               \
    asm volatile(                                                                 \
        "{\n\t.reg .pred p;\n\t"                                                  \
        "mbarrier.try_wait.parity.acquire.cta.shared::cta.b64 p, [%1], %2;\n\t"   \
        "selp.b32 %0, 1, 0, p;\n\t}"                                              \
        : "=r"(_done) : "r"(_mbar), "r"(_par) : "memory");                        \
    if (!_done) {                                                                 \
        asm volatile(                                                             \
            "{\n\t.reg .pred P1;\n\t"                                             \
            "WAIT_LOOP_%=:\n\t"                                                   \
            "mbarrier.try_wait.parity.acquire.cta.shared::cta.b64 P1, [%0], %1, 0x989680;\n\t" \
            "@P1 bra.uni WAIT_DONE_%=;\n\t"                                       \
            "bra.uni WAIT_LOOP_%=;\n\t"                                           \
            "WAIT_DONE_%=:\n\t}"                                                  \
            :: "r"(_mbar), "r"(_par) : "memory");                                 \
    }                                                                             \
} while (0)

#define MBARRIER_WAIT_PARITY_RELAXED(mbar, parity) do {                           \
    uint32_t _mbar = (uint32_t)(mbar);                                            \
    uint32_t _par = (uint32_t)(parity);                                           \
    uint32_t _done;                                                               \
    asm volatile(                                                                 \
        "{\n\t.reg .pred p;\n\t"                                                  \
        "mbarrier.try_wait.parity.relaxed.cta.shared::cta.b64 p, [%1], %2, 0x989680;\n\t" \
        "selp.b32 %0, 1, 0, p;\n\t}"                                              \
        : "=r"(_done) : "r"(_mbar), "r"(_par) : "memory");                        \
    if (!_done) {                                                                 \
        asm volatile(                                                             \
            "{\n\t.reg .pred P1;\n\t"                                             \
            "WAIT_LOOP_%=:\n\t"                                                   \
            "mbarrier.try_wait.parity.relaxed.cta.shared::cta.b64 P1, [%0], %1, 0x989680;\n\t" \
            "@P1 bra.uni WAIT_DONE_%=;\n\t"                                       \
            "bra.uni WAIT_LOOP_%=;\n\t"                                           \
            "WAIT_DONE_%=:\n\t}"                                                  \
            :: "r"(_mbar), "r"(_par) : "memory");                                 \
    }                                                                             \
} while (0)

#define BULK_G2S(dst_smem, src_gmem, nbytes, mbar)                                \
    asm volatile(                                                                 \
        "cp.async.bulk.shared::cta.global.mbarrier::complete_tx::bytes "          \
        "[%0], [%1], %2, [%3];"                                                   \
        :: "r"((uint32_t)(dst_smem)), "l"(src_gmem),                              \
           "r"((uint32_t)(nbytes)), "r"((uint32_t)(mbar)) : "memory")

// ============================================================================
// Pre-pass kernels (identical to validated R5)
// ============================================================================
__global__ void scatter_kernel(const float* __restrict__ vals,
                               const int* __restrict__ rows,
                               const int* __restrict__ cols, int nnz) {
    int i = blockIdx.x * blockDim.x + threadIdx.x;
    if (i < nnz) {
        int r = rows[i], c = cols[i];
        int kb = c >> 5, j = c & 31, kk = j >> 3, jj = j & 7;
        int p = (jj < 4) ? (jj << 1) : (((jj - 4) << 1) | 1);
        int cc = ((kk ^ (r & 3)) << 3) | p;
        atomicAdd(&g_W[(size_t)kb * (M_DIM * 32) + (size_t)r * 32 + cc], vals[i]);
    }
}

__global__ void round_w_kernel() {
    size_t n4 = (size_t)M_DIM * K_DIM / 4;
    float4* p = reinterpret_cast<float4*>(g_W);
    for (size_t i = blockIdx.x * blockDim.x + threadIdx.x; i < n4;
         i += (size_t)gridDim.x * blockDim.x) {
        float4 v = p[i];
        v.x = tf32_rna(v.x); v.y = tf32_rna(v.y);
        v.z = tf32_rna(v.z); v.w = tf32_rna(v.w);
        p[i] = v;
    }
}

__global__ void conv_x_kernel(const float* __restrict__ x) {
    size_t ngroups = (size_t)N_DIM * (K_DIM / 8);
    for (size_t i = blockIdx.x * blockDim.x + threadIdx.x; i < ngroups;
         i += (size_t)gridDim.x * blockDim.x) {
        int n  = (int)(i >> 9);            // K/8 = 512 groups per row
        int k8 = (int)(i & 511);
        int kb = k8 >> 2, kk = k8 & 3;
        const float4* src = reinterpret_cast<const float4*>(x + (size_t)n * K_DIM + k8 * 8);
        float4 v0 = src[0];                // k0..k3
        float4 v1 = src[1];                // k4..k7
        float4 o0, o1;
        o0.x = tf32_rna(v0.x); o0.y = tf32_rna(v1.x);   // k0,k4
        o0.z = tf32_rna(v0.y); o0.w = tf32_rna(v1.y);   // k1,k5
        o1.x = tf32_rna(v0.z); o1.y = tf32_rna(v1.z);   // k2,k6
        o1.z = tf32_rna(v0.w); o1.w = tf32_rna(v1.w);   // k3,k7
        float* dst = g_X + (size_t)kb * (N_DIM * 32) + (size_t)n * 32
                         + ((kk ^ (n & 3)) << 3);
        reinterpret_cast<float4*>(dst)[0] = o0;
        reinterpret_cast<float4*>(dst)[1] = o1;
    }
}

// ============================================================================
// Mainloop body: warp tile 64(m) x 32(n) -> 4 mi x 4 ni of m16n8k8.
// Per kk: 8 A-loads + 4 B-loads, 16 MMAs. All SMEM offsets literal immediates.
// ============================================================================
#define MMA_ROWS(ni, bf)                                                        \
    mma_tf32(acc[0][ni], alo0.x, ahi0.x, alo0.y, ahi0.y, (bf).x, (bf).y);       \
    mma_tf32(acc[1][ni], alo1.x, ahi1.x, alo1.y, ahi1.y, (bf).x, (bf).y);       \
    mma_tf32(acc[2][ni], alo2.x, ahi2.x, alo2.y, ahi2.y, (bf).x, (bf).y);       \
    mma_tf32(acc[3][ni], alo3.x, ahi3.x, alo3.y, ahi3.y, (bf).x, (bf).y);

#define KK_BLOCK(S, KKI) do {                                                   \
    uint2 alo0 = lds64i<(S)*STAGE_BYTES +    0>(aAddr[KKI]);                    \
    uint2 ahi0 = lds64i<(S)*STAGE_BYTES + 1024>(aAddr[KKI]);                    \
    uint2 alo1 = lds64i<(S)*STAGE_BYTES + 2048>(aAddr[KKI]);                    \
    uint2 ahi1 = lds64i<(S)*STAGE_BYTES + 3072>(aAddr[KKI]);                    \
    uint2 alo2 = lds64i<(S)*STAGE_BYTES + 4096>(aAddr[KKI]);                    \
    uint2 ahi2 = lds64i<(S)*STAGE_BYTES + 5120>(aAddr[KKI]);                    \
    uint2 alo3 = lds64i<(S)*STAGE_BYTES + 6144>(aAddr[KKI]);                    \
    uint2 ahi3 = lds64i<(S)*STAGE_BYTES + 7168>(aAddr[KKI]);                    \
    uint2 b0 = lds64i<(S)*STAGE_BYTES +    0>(bAddr[KKI]);                      \
    uint2 b1 = lds64i<(S)*STAGE_BYTES + 1024>(bAddr[KKI]);                      \
    uint2 b2 = lds64i<(S)*STAGE_BYTES + 2048>(bAddr[KKI]);                      \
    uint2 b3 = lds64i<(S)*STAGE_BYTES + 3072>(bAddr[KKI]);                      \
    MMA_ROWS(0, b0); MMA_ROWS(1, b1); MMA_ROWS(2, b2); MMA_ROWS(3, b3);         \
} while (0)

#define CONSUME_STAGE(S) do {                                                   \
    MBARRIER_WAIT_PARITY(sbase + MB_FULL(S), ph);                               \
    KK_BLOCK(S, 0); KK_BLOCK(S, 1); KK_BLOCK(S, 2); KK_BLOCK(S, 3);             \
    __syncwarp();                                                               \
    if (lane == 0) MBARRIER_ARRIVE(sbase + MB_EMPTY(S));                        \
} while (0)

// ============================================================================
// Warp-specialized tf32 GEMM: out[b,m,s] = sum_k W[m,k]*X[n,k] + bias[s]
// CTA tile 256x128; 16 consumer warps (4 per SMSP) + 1 producer.
// ============================================================================
__global__ void __launch_bounds__(THREADS, 1) gemm_kernel(
    const float* __restrict__ bias, float* __restrict__ out)
{
    extern __shared__ uint32_t smem[];
    const uint32_t sbase = smem_u32(smem);

    const int tid  = threadIdx.x;
    const int wid  = tid >> 5;
    const int lane = tid & 31;

    // CTA tile mapping: bid = mt + 16*nt (wave covers all 16 m-tiles -> A reuse)
    const int mt = blockIdx.x & 15;
    const int nt = blockIdx.x >> 4;
    const int m0 = mt * BM;
    const int n0 = nt * BN;

    if (tid == 0) {
        #pragma unroll
        for (int s = 0; s < STAGES; s++) {
            MBARRIER_INIT(sbase + MB_FULL(s), 1);
            MBARRIER_INIT(sbase + MB_EMPTY(s), 16);
        }
    }
    __syncthreads();

    if (wid == 16) {
        // ------------------------- Producer warp -------------------------
        if (elect_one_pred()) {
            const float* Asrc0 = g_W + (size_t)m0 * 32;
            const float* Bsrc0 = g_X + (size_t)n0 * 32;
            int ph = 1;   // fresh barriers: parity-1 waits pass
            for (int ko = 0; ko < K_OUTER; ko++) {
                #pragma unroll
                for (int s = 0; s < STAGES; s++) {
                    const int k = ko * STAGES + s;
                    MBARRIER_WAIT_PARITY_RELAXED(sbase + MB_EMPTY(s), ph);
                    uint32_t full = sbase + MB_FULL(s);
                    uint32_t dst  = sbase + SMEM_STAGE0 + s * STAGE_BYTES;
                    MBARRIER_EXPECT_TX(full, STAGE_BYTES);
                    BULK_G2S(dst, Asrc0 + (size_t)k * (M_DIM * 32),
                             A_STAGE_BYTES, full);
                    BULK_G2S(dst + A_STAGE_BYTES, Bsrc0 + (size_t)k * (N_DIM * 32),
                             B_STAGE_BYTES, full);
                }
                ph ^= 1;
            }
        }
        return;
    }

    // --------------------------- Consumer warps ---------------------------
    const int g  = lane >> 2;       // fragment row group 0..7
    const int t  = lane & 3;        // fragment col group 0..3
    const int gx = g & 3;           // XOR swizzle key
    const int wm = wid & 3;         // warp m index 0..3 (64 rows each)
    const int wn = wid >> 2;        // warp n index 0..3 (32 rows each)

    // Per-kk stage-0 base addresses; stage & mi/ni offsets are LDS immediates.
    uint32_t aAddr[4], bAddr[4];
    {
        const uint32_t aBase = sbase + SMEM_STAGE0
                             + (uint32_t)((wm * 64 + g) * 128 + t * 8);
        const uint32_t bBase = sbase + SMEM_STAGE0 + A_STAGE_BYTES
                             + (uint32_t)((wn * 32 + g) * 128 + t * 8);
        #pragma unroll
        for (int kk = 0; kk < 4; kk++) {
            const uint32_t kx = (uint32_t)(((kk ^ gx) & 3) << 5);
            aAddr[kk] = aBase + kx;
            bAddr[kk] = bBase + kx;
        }
    }

    float acc[4][4][4];
#pragma unroll
    for (int i = 0; i < 4; i++)
#pragma unroll
        for (int j = 0; j < 4; j++)
#pragma unroll
            for (int r = 0; r < 4; r++) acc[i][j][r] = 0.0f;

    int ph = 0;
    for (int ko = 0; ko < K_OUTER; ko++) {
        CONSUME_STAGE(0);
        CONSUME_STAGE(1);
        CONSUME_STAGE(2);
        CONSUME_STAGE(3);
        ph ^= 1;
    }

    // ------------------------------------------------------------------------
    // Epilogue: out[b, m, s] = acc + bias[s]; CTA tile lies in one batch
    // ------------------------------------------------------------------------
    const int b   = n0 >> 11;        // n0 / 2048
    const int s0c = n0 & 2047;
    float* obase = out + (size_t)b * M_DIM * S_DIM;

#pragma unroll
    for (int mi = 0; mi < 4; mi++) {
#pragma unroll
        for (int ni = 0; ni < 4; ni++) {
            int sl = s0c + wn * 32 + ni * 8 + 2 * t;
            float2 bv = *reinterpret_cast<const float2*>(bias + sl);
            int m = m0 + wm * 64 + mi * 16 + g;

            float2 v0;
            v0.x = acc[mi][ni][0] + bv.x;
            v0.y = acc[mi][ni][1] + bv.y;
            *reinterpret_cast<float2*>(obase + (size_t)m * S_DIM + sl) = v0;

            float2 v1;
            v1.x = acc[mi][ni][2] + bv.x;
            v1.y = acc[mi][ni][3] + bv.y;
            *reinterpret_cast<float2*>(obase + (size_t)(m + 8) * S_DIM + sl) = v1;
        }
    }
}

// ============================================================================
// Host launch
// ============================================================================
extern "C" void kernel_launch(void* const* d_in, const int* in_sizes, int n_in,
                              void* d_out, int out_size) {
    const float* x      = (const float*)d_in[0];
    const float* values = (const float*)d_in[1];
    const float* bias   = (const float*)d_in[2];
    const int* row_ids  = (const int*)d_in[3];
    const int* col_idx  = (const int*)d_in[4];
    int nnz = in_sizes[1];
    float* out = (float*)d_out;

    void* wptr = nullptr;
    cudaGetSymbolAddress(&wptr, g_W);

    // 1) zero W (each replay re-accumulates from zero)
    cudaMemsetAsync(wptr, 0, (size_t)M_DIM * K_DIM * sizeof(float));

    // 2) scatter-add COO values directly into blocked+swizzled W
    scatter_kernel<<<(nnz + 255) / 256, 256>>>(values, row_ids, col_idx, nnz);

    // 3) tf32-round W in place; build blocked+swizzled tf32 X
    round_w_kernel<<<2048, 256>>>();
    conv_x_kernel<<<4096, 256>>>(x);

    // 4) GEMM: grid = 16 m-tiles * 128 n-tiles
    cudaFuncSetAttribute(gemm_kernel,
                         cudaFuncAttributeMaxDynamicSharedMemorySize,
                         SMEM_BYTES);
    gemm_kernel<<<(M_DIM / BM) * (N_DIM / BN), THREADS, SMEM_BYTES>>>(bias, out);
}